// round 7
// baseline (speedup 1.0000x reference)
#include <cuda_runtime.h>
#include <math.h>
#include <stdint.h>

#define BB 32
#define TT_LEN 2048
#define DD 512
#define NH 1024        // complex FFT length (real length 2048)
#define KSEL 16
#define TTILE 256
#define NM (TT_LEN / TTILE)   // 8
#define PI_D 3.14159265358979323846

// padded smem indexing: kills store bank conflicts in Stockham passes
#define IDX(i) ((i) + ((i) >> 5))
#define PADN (NH + NH / 32)   // 1056

// ---------------- device scratch ------------------------------------------
__device__ float  d_xt[(size_t)BB * DD * TT_LEN];   // transposed input [b][d][t]
__device__ float2 d_twf[256];        // w  = exp(-2pi i j / 1024)
__device__ float2 d_twf2[256];       // w^2
__device__ float2 d_twf3[256];       // w^3
__device__ float2 d_twu[NH];         // untangle twiddles exp(-2pi i k / 2048)
__device__ float  d_cwT[NH];         // cos(omega_k)
__device__ float  d_swT[NH];         // sin(omega_k)
__device__ float  d_eT[NH];          // -4 sin^2(omega_k/2)  (Reinsch coefficient)
__device__ float2 d_rot0[NM * NH];   // e^{i omega_k * TTILE * m}
__device__ float  d_c0[BB * DD * KSEL];
__device__ float  d_s0[BB * DD * KSEL];
__device__ int    d_kix[BB * DD * KSEL];

// ---------------- packed f32x2 helpers ------------------------------------
typedef unsigned long long u64;
__device__ __forceinline__ u64 pk(float lo, float hi) {
    u64 r; asm("mov.b64 %0,{%1,%2};" : "=l"(r) : "f"(lo), "f"(hi)); return r;
}
__device__ __forceinline__ void upk(u64 v, float& lo, float& hi) {
    asm("mov.b64 {%0,%1},%2;" : "=f"(lo), "=f"(hi) : "l"(v));
}
#define F2ADD(d,a,b)   asm("add.rn.f32x2 %0,%1,%2;"    : "=l"(d) : "l"(a), "l"(b))
#define F2FMA(d,a,b,c) asm("fma.rn.f32x2 %0,%1,%2,%3;" : "=l"(d) : "l"(a), "l"(b), "l"(c))

// ---------------- init: all tables (double precision) ---------------------
__global__ void init_tables() {
    int gid = blockIdx.x * blockDim.x + threadIdx.x;   // 64*256 = 16384
    if (gid < 256) {
        double a = -2.0 * PI_D * (double)gid / (double)NH;
        d_twf[gid]  = make_float2((float)cos(a), (float)sin(a));
        d_twf2[gid] = make_float2((float)cos(2 * a), (float)sin(2 * a));
        d_twf3[gid] = make_float2((float)cos(3 * a), (float)sin(3 * a));
    }
    if (gid < NH) {
        double a = -2.0 * PI_D * (double)gid / (double)(2 * NH);
        d_twu[gid] = make_float2((float)cos(a), (float)sin(a));
        double om = 2.0 * PI_D * (double)gid / ((double)TT_LEN * (double)(TT_LEN - 1));
        d_cwT[gid] = (float)cos(om);
        d_swT[gid] = (float)sin(om);
        double sh = sin(om * 0.5);
        d_eT[gid]  = (float)(-4.0 * sh * sh);
    }
    if (gid < NM * NH) {
        int m = gid >> 10, k = gid & (NH - 1);
        double om = 2.0 * PI_D * (double)k / ((double)TT_LEN * (double)(TT_LEN - 1));
        double a = om * (double)(TTILE * m);
        d_rot0[gid] = make_float2((float)cos(a), (float)sin(a));
    }
}

// ---------------- transpose: x[b][t][d] -> d_xt[b][d][t] -------------------
__global__ __launch_bounds__(256) void transpose(const float* __restrict__ x) {
    __shared__ float tile[32][33];
    const int b  = blockIdx.z;
    const int t0 = blockIdx.x * 32;
    const int d0 = blockIdx.y * 32;
    const int lx = threadIdx.x;
    const int ly = threadIdx.y;
#pragma unroll
    for (int i = 0; i < 32; i += 8)
        tile[ly + i][lx] = x[((size_t)b * TT_LEN + t0 + ly + i) * DD + d0 + lx];
    __syncthreads();
#pragma unroll
    for (int i = 0; i < 32; i += 8)
        d_xt[((size_t)b * DD + d0 + ly + i) * TT_LEN + t0 + lx] = tile[lx][ly + i];
}

__device__ __forceinline__ float2 cmulf(float2 a, float2 b) {
    return make_float2(a.x * b.x - a.y * b.y, a.x * b.y + a.y * b.x);
}
__device__ __forceinline__ float2 cadd(float2 a, float2 b) { return make_float2(a.x + b.x, a.y + b.y); }
__device__ __forceinline__ float2 csub(float2 a, float2 b) { return make_float2(a.x - b.x, a.y - b.y); }

// Real-FFT bin k (1..1023) from packed complex spectrum Z (padded layout).
__device__ __forceinline__ float2 untangle(const float2* Z, int k) {
    float2 A  = Z[IDX(k)];
    float2 Bv = Z[IDX(NH - k)];
    float2 Bc = make_float2(Bv.x, -Bv.y);
    float2 E  = make_float2(0.5f * (A.x + Bc.x), 0.5f * (A.y + Bc.y));
    float2 Od = make_float2(A.x - Bc.x, A.y - Bc.y);
    float2 O  = make_float2(0.5f * Od.y, -0.5f * Od.x);
    float2 eo = cmulf(d_twu[k], O);
    return make_float2(E.x + eo.x, E.y + eo.y);
}

// One radix-4 Stockham pass.  Final pass (M=256) has w=1: no twiddle mults.
template <int M>
__device__ __forceinline__ void fft_pass(const float2* __restrict__ X,
                                         float2* __restrict__ Y, int tid) {
    float2 a = X[IDX(tid)];
    float2 b = X[IDX(tid + 256)];
    float2 c = X[IDX(tid + 512)];
    float2 d = X[IDX(tid + 768)];
    float2 t0 = cadd(a, c);
    float2 t1 = csub(a, c);
    float2 t2 = cadd(b, d);
    float2 e  = csub(b, d);
    float2 t3 = make_float2(e.y, -e.x);        // -i * (b - d)
    int wb = 4 * (tid & ~(M - 1)) + (tid & (M - 1));
    if constexpr (M == 256) {
        Y[IDX(wb)]         = cadd(t0, t2);
        Y[IDX(wb + M)]     = cadd(t1, t3);
        Y[IDX(wb + 2 * M)] = csub(t0, t2);
        Y[IDX(wb + 3 * M)] = csub(t1, t3);
    } else {
        int j = tid & ~(M - 1);
        float2 w  = d_twf[j];
        float2 w2 = d_twf2[j];
        float2 w3 = d_twf3[j];
        Y[IDX(wb)]         = cadd(t0, t2);
        Y[IDX(wb + M)]     = cmulf(w,  cadd(t1, t3));
        Y[IDX(wb + 2 * M)] = cmulf(w2, csub(t0, t2));
        Y[IDX(wb + 3 * M)] = cmulf(w3, csub(t1, t3));
    }
}

// ---------------- analysis: 2 channels per block ---------------------------
__global__ __launch_bounds__(256) void analyze() {
    __shared__ float2   bufA0[PADN], bufB0[PADN];
    __shared__ float2   bufA1[PADN], bufB1[PADN];
    __shared__ unsigned cand_v[2][8 * KSEL];
    __shared__ int      cand_k[2][8 * KSEL];
    __shared__ int      sel[2][KSEL];

    const int tid = threadIdx.x;
    const int ch0 = blockIdx.x * 2;
    const float4* row0 = (const float4*)(d_xt + (size_t)ch0 * TT_LEN);
    const float4* row1 = (const float4*)(d_xt + (size_t)(ch0 + 1) * TT_LEN);

#pragma unroll
    for (int q = 0; q < 2; q++) {
        int j = tid + 256 * q;
        float4 v0 = row0[j];
        float4 v1 = row1[j];
        bufA0[IDX(2 * j)]     = make_float2(v0.x, v0.y);
        bufA0[IDX(2 * j + 1)] = make_float2(v0.z, v0.w);
        bufA1[IDX(2 * j)]     = make_float2(v1.x, v1.y);
        bufA1[IDX(2 * j + 1)] = make_float2(v1.z, v1.w);
    }
    __syncthreads();

    fft_pass<1>(bufA0, bufB0, tid);   fft_pass<1>(bufA1, bufB1, tid);   __syncthreads();
    fft_pass<4>(bufB0, bufA0, tid);   fft_pass<4>(bufB1, bufA1, tid);   __syncthreads();
    fft_pass<16>(bufA0, bufB0, tid);  fft_pass<16>(bufA1, bufB1, tid);  __syncthreads();
    fft_pass<64>(bufB0, bufA0, tid);  fft_pass<64>(bufB1, bufA1, tid);  __syncthreads();
    fft_pass<256>(bufA0, bufB0, tid); fft_pass<256>(bufA1, bufB1, tid); __syncthreads();
    // spectra in bufB0 / bufB1 (natural order)

    // per-thread mags (monotonic uint bits), 4 bins per channel; bin 0 -> 0
    unsigned a0, a1, a2, a3, b0, b1, b2, b3;
    int ka0 = tid, ka1 = tid + 256, ka2 = tid + 512, ka3 = tid + 768;
    int kb0 = tid, kb1 = tid + 256, kb2 = tid + 512, kb3 = tid + 768;
    {
        float2 X;
        X = untangle(bufB0, ka1); a1 = __float_as_uint(X.x * X.x + X.y * X.y);
        X = untangle(bufB0, ka2); a2 = __float_as_uint(X.x * X.x + X.y * X.y);
        X = untangle(bufB0, ka3); a3 = __float_as_uint(X.x * X.x + X.y * X.y);
        X = untangle(bufB1, kb1); b1 = __float_as_uint(X.x * X.x + X.y * X.y);
        X = untangle(bufB1, kb2); b2 = __float_as_uint(X.x * X.x + X.y * X.y);
        X = untangle(bufB1, kb3); b3 = __float_as_uint(X.x * X.x + X.y * X.y);
        if (tid == 0) { a0 = 0u; b0 = 0u; }
        else {
            X = untangle(bufB0, ka0); a0 = __float_as_uint(X.x * X.x + X.y * X.y);
            X = untangle(bufB1, kb0); b0 = __float_as_uint(X.x * X.x + X.y * X.y);
        }
    }

#define CSWP(a, b, ka, kb) if (a < b) { unsigned tu = a; a = b; b = tu; int tk = ka; ka = kb; kb = tk; }
    CSWP(a0, a1, ka0, ka1)  CSWP(a2, a3, ka2, ka3)
    CSWP(a0, a2, ka0, ka2)  CSWP(a1, a3, ka1, ka3)
    CSWP(a1, a2, ka1, ka2)
    CSWP(b0, b1, kb0, kb1)  CSWP(b2, b3, kb2, kb3)
    CSWP(b0, b2, kb0, kb2)  CSWP(b1, b3, kb1, kb3)
    CSWP(b1, b2, kb1, kb2)
#undef CSWP

    const int lane = tid & 31;
    const int warp = tid >> 5;
    const unsigned FULL = 0xffffffffu;

    // phase 1: per-warp top-16 for both channels (independent REDUX streams)
    for (int r = 0; r < KSEL; r++) {
        unsigned mxa = __reduce_max_sync(FULL, a0);
        unsigned mxb = __reduce_max_sync(FULL, b0);
        unsigned bla = __ballot_sync(FULL, a0 == mxa);
        unsigned blb = __ballot_sync(FULL, b0 == mxb);
        int wla = __ffs((int)bla) - 1;
        int wlb = __ffs((int)blb) - 1;
        if (lane == wla) {
            cand_v[0][warp * KSEL + r] = a0;
            cand_k[0][warp * KSEL + r] = ka0;
            a0 = a1; ka0 = ka1;  a1 = a2; ka1 = ka2;  a2 = a3; ka2 = ka3;  a3 = 0u;
        }
        if (lane == wlb) {
            cand_v[1][warp * KSEL + r] = b0;
            cand_k[1][warp * KSEL + r] = kb0;
            b0 = b1; kb0 = kb1;  b1 = b2; kb1 = kb2;  b2 = b3; kb2 = kb3;  b3 = 0u;
        }
    }
    __syncthreads();

    // phase 2: warp 0 merges ch0, warp 1 merges ch1 (parallel)
    if (warp < 2) {
        const int c = warp;
        int ptr = 0, curk = 0;
        unsigned hv = 0u;
        if (lane < 8) { hv = cand_v[c][lane * KSEL]; curk = cand_k[c][lane * KSEL]; }
        for (int r = 0; r < KSEL; r++) {
            unsigned mx = __reduce_max_sync(FULL, hv);
            unsigned ball = __ballot_sync(FULL, hv == mx);
            int wl = __ffs((int)ball) - 1;
            int kwin = __shfl_sync(FULL, curk, wl);
            if (lane == 0) sel[c][r] = kwin;
            if (lane == wl) {
                ptr++;
                if (ptr < KSEL) {
                    hv = cand_v[c][lane * KSEL + ptr];
                    curk = cand_k[c][lane * KSEL + ptr];
                } else {
                    hv = 0u;
                }
            }
        }
    }
    __syncthreads();

    // emit: warp 0 lanes 0-15 -> ch0, warp 1 lanes 0-15 -> ch1
    if (warp < 2 && lane < KSEL) {
        const int c = warp;
        int k = sel[c][lane];
        float2 Xk = untangle(c == 0 ? bufB0 : bufB1, k);
        int base = (ch0 + c) * KSEL + lane;
        d_c0[base]  = Xk.x;
        d_s0[base]  = Xk.y;
        d_kix[base] = k;
    }
}

// ---------------- synthesis: packed-f32x2 Reinsch oscillator --------------
// d_{t+1} = d_t + e*y_t ;  y_{t+1} = y_t + d_{t+1} ;  e = -4 sin^2(w/2)
__global__ __launch_bounds__(128, 7) void synth(float* __restrict__ out) {
    const int b  = blockIdx.z;
    const int d  = blockIdx.y * 128 + threadIdx.x;
    const int m  = blockIdx.x;
    const int base = (b * DD + d) * KSEL;
    const float2* rot = d_rot0 + m * NH;

    float ys[KSEL], dss[KSEL], es[KSEL];
#pragma unroll
    for (int r = 0; r < KSEL; r++) {
        int    k  = d_kix[base + r];
        float  c0 = d_c0[base + r];
        float  s0 = d_s0[base + r];
        float2 rk = rot[k];
        float  y  = fmaf(c0, rk.x, -s0 * rk.y);      // A cos(theta0)
        float  sn = fmaf(c0, rk.y,  s0 * rk.x);      // A sin(theta0)
        float  cw = d_cwT[k];
        float  sw = d_swT[k];
        float  yp = fmaf(y, cw, sn * sw);            // A cos(theta0 - w)
        ys[r]  = y;
        dss[r] = y - yp;
        es[r]  = d_eT[k];
    }

    u64 Y[8], D[8], E[8];
#pragma unroll
    for (int p = 0; p < 8; p++) {
        Y[p] = pk(ys[2 * p],  ys[2 * p + 1]);
        D[p] = pk(dss[2 * p], dss[2 * p + 1]);
        E[p] = pk(es[2 * p],  es[2 * p + 1]);
    }

    float* po = out + ((size_t)b * TT_LEN + m * TTILE) * DD + d;
#pragma unroll 4
    for (int tt = 0; tt < TTILE; tt++) {
        u64 q0, q1, q2, q3;
        F2ADD(q0, Y[0], Y[1]);
        F2ADD(q1, Y[2], Y[3]);
        F2ADD(q2, Y[4], Y[5]);
        F2ADD(q3, Y[6], Y[7]);
        F2ADD(q0, q0, q1);
        F2ADD(q2, q2, q3);
        F2ADD(q0, q0, q2);
        float lo, hi;
        upk(q0, lo, hi);
        po[(size_t)tt * DD] = lo + hi;

        // Reinsch advance: D += E*Y ; Y += D
#pragma unroll
        for (int p = 0; p < 8; p++) {
            F2FMA(D[p], E[p], Y[p], D[p]);
            F2ADD(Y[p], Y[p], D[p]);
        }
    }
}

// ---------------- launch ---------------------------------------------------
extern "C" void kernel_launch(void* const* d_in, const int* in_sizes, int n_in,
                              void* d_out, int out_size) {
    const float* x = (const float*)d_in[0];
    float* out = (float*)d_out;

    init_tables<<<64, 256>>>();
    transpose<<<dim3(TT_LEN / 32, DD / 32, BB), dim3(32, 8)>>>(x);
    analyze<<<BB * DD / 2, 256>>>();
    synth<<<dim3(NM, DD / 128, BB), 128>>>(out);
}

// round 8
// speedup vs baseline: 1.1382x; 1.1382x over previous
#include <cuda_runtime.h>
#include <math.h>
#include <stdint.h>

#define BB 32
#define TT_LEN 2048
#define DD 512
#define NH 1024        // complex FFT length (real length 2048)
#define KSEL 16
#define TTILE 256
#define NM (TT_LEN / TTILE)   // 8
#define PI_D 3.14159265358979323846

// padded smem indexing (pad every 16 float2): conflict-free for all three
// access patterns (stride-16 writes, u+64q"+256q reads, stage-B writes)
#define IDX(i) ((i) + ((i) >> 4))
#define PADN (NH + NH / 16)   // 1088

// ---------------- device scratch ------------------------------------------
__device__ float  d_xt[(size_t)BB * DD * TT_LEN];   // transposed input [b][d][t]
__device__ float2 d_twf[256];        // w   = exp(-2pi i j / 1024)
__device__ float2 d_twf2[256];       // w^2
__device__ float2 d_twf3[256];       // w^3
__device__ float2 d_twu[NH];         // untangle twiddles exp(-2pi i k / 2048)
__device__ float  d_cwT[NH];         // cos(omega_k)
__device__ float  d_swT[NH];         // sin(omega_k)
__device__ float  d_eT[NH];          // -4 sin^2(omega_k/2)  (Reinsch coefficient)
__device__ float2 d_rot0[NM * NH];   // e^{i omega_k * TTILE * m}
__device__ float  d_c0[BB * DD * KSEL];
__device__ float  d_s0[BB * DD * KSEL];
__device__ int    d_kix[BB * DD * KSEL];

// ---------------- packed f32x2 helpers ------------------------------------
typedef unsigned long long u64;
__device__ __forceinline__ u64 pk(float lo, float hi) {
    u64 r; asm("mov.b64 %0,{%1,%2};" : "=l"(r) : "f"(lo), "f"(hi)); return r;
}
__device__ __forceinline__ void upk(u64 v, float& lo, float& hi) {
    asm("mov.b64 {%0,%1},%2;" : "=f"(lo), "=f"(hi) : "l"(v));
}
#define F2ADD(d,a,b)   asm("add.rn.f32x2 %0,%1,%2;"    : "=l"(d) : "l"(a), "l"(b))
#define F2FMA(d,a,b,c) asm("fma.rn.f32x2 %0,%1,%2,%3;" : "=l"(d) : "l"(a), "l"(b), "l"(c))

// ---------------- init: all tables (double precision) ---------------------
__global__ void init_tables() {
    int gid = blockIdx.x * blockDim.x + threadIdx.x;   // 64*256 = 16384
    if (gid < 256) {
        double a = -2.0 * PI_D * (double)gid / (double)NH;
        d_twf[gid]  = make_float2((float)cos(a), (float)sin(a));
        d_twf2[gid] = make_float2((float)cos(2 * a), (float)sin(2 * a));
        d_twf3[gid] = make_float2((float)cos(3 * a), (float)sin(3 * a));
    }
    if (gid < NH) {
        double a = -2.0 * PI_D * (double)gid / (double)(2 * NH);
        d_twu[gid] = make_float2((float)cos(a), (float)sin(a));
        double om = 2.0 * PI_D * (double)gid / ((double)TT_LEN * (double)(TT_LEN - 1));
        d_cwT[gid] = (float)cos(om);
        d_swT[gid] = (float)sin(om);
        double sh = sin(om * 0.5);
        d_eT[gid]  = (float)(-4.0 * sh * sh);
    }
    if (gid < NM * NH) {
        int m = gid >> 10, k = gid & (NH - 1);
        double om = 2.0 * PI_D * (double)k / ((double)TT_LEN * (double)(TT_LEN - 1));
        double a = om * (double)(TTILE * m);
        d_rot0[gid] = make_float2((float)cos(a), (float)sin(a));
    }
}

// ---------------- transpose: x[b][t][d] -> d_xt[b][d][t] -------------------
__global__ __launch_bounds__(256) void transpose(const float* __restrict__ x) {
    __shared__ float tile[32][33];
    const int b  = blockIdx.z;
    const int t0 = blockIdx.x * 32;
    const int d0 = blockIdx.y * 32;
    const int lx = threadIdx.x;
    const int ly = threadIdx.y;
#pragma unroll
    for (int i = 0; i < 32; i += 8)
        tile[ly + i][lx] = x[((size_t)b * TT_LEN + t0 + ly + i) * DD + d0 + lx];
    __syncthreads();
#pragma unroll
    for (int i = 0; i < 32; i += 8)
        d_xt[((size_t)b * DD + d0 + ly + i) * TT_LEN + t0 + lx] = tile[lx][ly + i];
}

__device__ __forceinline__ float2 cmulf(float2 a, float2 b) {
    return make_float2(a.x * b.x - a.y * b.y, a.x * b.y + a.y * b.x);
}
__device__ __forceinline__ float2 cadd(float2 a, float2 b) { return make_float2(a.x + b.x, a.y + b.y); }
__device__ __forceinline__ float2 csub(float2 a, float2 b) { return make_float2(a.x - b.x, a.y - b.y); }

// radix-4 butterfly with twiddles (w, w^2, w^3); DIT form matching pass-M algebra
__device__ __forceinline__ void bfly4(float2 a, float2 b, float2 c, float2 d,
                                      float2 w1, float2 w2, float2 w3,
                                      float2& o0, float2& o1, float2& o2, float2& o3) {
    float2 t0 = cadd(a, c);
    float2 t1 = csub(a, c);
    float2 t2 = cadd(b, d);
    float2 e  = csub(b, d);
    float2 t3 = make_float2(e.y, -e.x);   // -i*(b-d)
    o0 = cadd(t0, t2);
    o1 = cmulf(w1, cadd(t1, t3));
    o2 = cmulf(w2, csub(t0, t2));
    o3 = cmulf(w3, csub(t1, t3));
}

// Real-FFT bin k (1..1023) from packed complex spectrum Z (padded layout).
__device__ __forceinline__ float2 untangle(const float2* Z, int k) {
    float2 A  = Z[IDX(k)];
    float2 Bv = Z[IDX(NH - k)];
    float2 Bc = make_float2(Bv.x, -Bv.y);
    float2 E  = make_float2(0.5f * (A.x + Bc.x), 0.5f * (A.y + Bc.y));
    float2 Od = make_float2(A.x - Bc.x, A.y - Bc.y);
    float2 O  = make_float2(0.5f * Od.y, -0.5f * Od.x);
    float2 eo = cmulf(d_twu[k], O);
    return make_float2(E.x + eo.x, E.y + eo.y);
}

// ---------------- analysis: fused-stage FFT, 4 channels / block -----------
// 64 threads per channel, 16 complex points per thread.
// Pass sequence (verified algebra): M=1,4 fused -> exchange -> M=16,64 fused
// -> exchange -> M=256 in place.
__global__ __launch_bounds__(256, 3) void analyze() {
    __shared__ float2   buf[4][PADN];
    __shared__ unsigned cand_v[4][8 * KSEL];
    __shared__ int      cand_k[4][8 * KSEL];
    __shared__ int      sel[4][KSEL];

    const int tid = threadIdx.x;
    const int u   = tid & 63;      // thread within channel
    const int c   = tid >> 6;      // channel within block
    const int ch  = blockIdx.x * 4 + c;
    const float2* row = (const float2*)(d_xt + (size_t)ch * TT_LEN);
    float2* B = buf[c];

    // ---- stage pair A: pass M=1 then M=4, fused in registers ----
    {
        float2 V[4][4];
#pragma unroll
        for (int qq = 0; qq < 4; qq++) {       // pass-1 thread t = u + 64*qq
            int t = u + 64 * qq;
            float2 a  = row[t];
            float2 b  = row[t + 256];
            float2 cc = row[t + 512];
            float2 dd = row[t + 768];
            bfly4(a, b, cc, dd, d_twf[t], d_twf2[t], d_twf3[t],
                  V[qq][0], V[qq][1], V[qq][2], V[qq][3]);
        }
        float2 w1 = d_twf[4 * u], w2 = d_twf2[4 * u], w3 = d_twf3[4 * u];
#pragma unroll
        for (int lam = 0; lam < 4; lam++) {    // pass-4 thread t' = 4u + lam
            float2 o0, o1, o2, o3;
            bfly4(V[0][lam], V[1][lam], V[2][lam], V[3][lam], w1, w2, w3,
                  o0, o1, o2, o3);
            B[IDX(16 * u +  0 + lam)] = o0;    // Y[16u + 4q' + lam]
            B[IDX(16 * u +  4 + lam)] = o1;
            B[IDX(16 * u +  8 + lam)] = o2;
            B[IDX(16 * u + 12 + lam)] = o3;
        }
    }
    __syncthreads();

    // ---- stage pair B: pass M=16 then M=64, fused ----
    {
        float2 R[4][4];
#pragma unroll
        for (int qq = 0; qq < 4; qq++)
#pragma unroll
            for (int q = 0; q < 4; q++)
                R[qq][q] = B[IDX(u + 64 * qq + 256 * q)];
        __syncthreads();                        // all reads before any write

        const int ub = u & ~15;                 // 16*h'
        float2 V[4][4];
#pragma unroll
        for (int qq = 0; qq < 4; qq++) {        // pass-16 thread t = u + 64*qq
            int j = ub + 64 * qq;
            bfly4(R[qq][0], R[qq][1], R[qq][2], R[qq][3],
                  d_twf[j], d_twf2[j], d_twf3[j],
                  V[qq][0], V[qq][1], V[qq][2], V[qq][3]);
        }
        int j2 = 4 * ub;
        float2 w1 = d_twf[j2], w2 = d_twf2[j2], w3 = d_twf3[j2];
        int basei = 16 * ub + (u & 15);
#pragma unroll
        for (int lam = 0; lam < 4; lam++) {     // pass-64 thread t' = 64h'+16lam+l
            float2 o0, o1, o2, o3;
            bfly4(V[0][lam], V[1][lam], V[2][lam], V[3][lam], w1, w2, w3,
                  o0, o1, o2, o3);
            B[IDX(basei + 16 * lam +   0)] = o0;
            B[IDX(basei + 16 * lam +  64)] = o1;
            B[IDX(basei + 16 * lam + 128)] = o2;
            B[IDX(basei + 16 * lam + 192)] = o3;
        }
    }
    __syncthreads();

    // ---- final pass M=256: per-thread in place (read set == write set) ----
#pragma unroll
    for (int qq = 0; qq < 4; qq++) {
        int t = u + 64 * qq;
        float2 a  = B[IDX(t)];
        float2 b  = B[IDX(t + 256)];
        float2 cc = B[IDX(t + 512)];
        float2 dd = B[IDX(t + 768)];
        float2 t0 = cadd(a, cc);
        float2 t1 = csub(a, cc);
        float2 t2 = cadd(b, dd);
        float2 e  = csub(b, dd);
        float2 t3 = make_float2(e.y, -e.x);
        B[IDX(t)]       = cadd(t0, t2);
        B[IDX(t + 256)] = cadd(t1, t3);
        B[IDX(t + 512)] = csub(t0, t2);
        B[IDX(t + 768)] = csub(t1, t3);
    }
    __syncthreads();
    // spectra for 4 channels in buf[0..3] (natural order, padded)

    // ---- mags: 4 bins per channel per thread, 4 channels ----
    unsigned uv[4][4];
    int      kv[4][4];
#pragma unroll
    for (int cc = 0; cc < 4; cc++) {
        const float2* Z = buf[cc];
        int b0 = tid, b1 = tid + 256, b2 = tid + 512, b3 = tid + 768;
        float2 X;
        unsigned m0;
        if (tid == 0) m0 = 0u;
        else { X = untangle(Z, b0); m0 = __float_as_uint(X.x * X.x + X.y * X.y); }
        X = untangle(Z, b1); unsigned m1 = __float_as_uint(X.x * X.x + X.y * X.y);
        X = untangle(Z, b2); unsigned m2 = __float_as_uint(X.x * X.x + X.y * X.y);
        X = untangle(Z, b3); unsigned m3 = __float_as_uint(X.x * X.x + X.y * X.y);
#define CSWP(a, b, ka, kb) if (a < b) { unsigned tu = a; a = b; b = tu; int tk = ka; ka = kb; kb = tk; }
        CSWP(m0, m1, b0, b1)
        CSWP(m2, m3, b2, b3)
        CSWP(m0, m2, b0, b2)
        CSWP(m1, m3, b1, b3)
        CSWP(m1, m2, b1, b2)
#undef CSWP
        uv[cc][0] = m0; uv[cc][1] = m1; uv[cc][2] = m2; uv[cc][3] = m3;
        kv[cc][0] = b0; kv[cc][1] = b1; kv[cc][2] = b2; kv[cc][3] = b3;
    }

    const int lane = tid & 31;
    const int warp = tid >> 5;
    const unsigned FULL = 0xffffffffu;

    // phase 1: per-warp top-16, 4 independent REDUX streams (one per channel)
    for (int r = 0; r < KSEL; r++) {
#pragma unroll
        for (int cc = 0; cc < 4; cc++) {
            unsigned mx = __reduce_max_sync(FULL, uv[cc][0]);
            unsigned ball = __ballot_sync(FULL, uv[cc][0] == mx);
            int wl = __ffs((int)ball) - 1;
            if (lane == wl) {
                cand_v[cc][warp * KSEL + r] = uv[cc][0];
                cand_k[cc][warp * KSEL + r] = kv[cc][0];
                uv[cc][0] = uv[cc][1]; kv[cc][0] = kv[cc][1];
                uv[cc][1] = uv[cc][2]; kv[cc][1] = kv[cc][2];
                uv[cc][2] = uv[cc][3]; kv[cc][2] = kv[cc][3];
                uv[cc][3] = 0u;
            }
        }
    }
    __syncthreads();

    // phase 2: warps 0-3 merge channels 0-3 in parallel
    if (warp < 4) {
        const int cc = warp;
        int ptr = 0, curk = 0;
        unsigned hv = 0u;
        if (lane < 8) { hv = cand_v[cc][lane * KSEL]; curk = cand_k[cc][lane * KSEL]; }
        for (int r = 0; r < KSEL; r++) {
            unsigned mx = __reduce_max_sync(FULL, hv);
            unsigned ball = __ballot_sync(FULL, hv == mx);
            int wl = __ffs((int)ball) - 1;
            int kwin = __shfl_sync(FULL, curk, wl);
            if (lane == 0) sel[cc][r] = kwin;
            if (lane == wl) {
                ptr++;
                if (ptr < KSEL) {
                    hv = cand_v[cc][lane * KSEL + ptr];
                    curk = cand_k[cc][lane * KSEL + ptr];
                } else {
                    hv = 0u;
                }
            }
        }
    }
    __syncthreads();

    // emit: warp w, lanes 0-15 -> channel w
    if (warp < 4 && lane < KSEL) {
        int k = sel[warp][lane];
        float2 Xk = untangle(buf[warp], k);
        int base = (blockIdx.x * 4 + warp) * KSEL + lane;
        d_c0[base]  = Xk.x;
        d_s0[base]  = Xk.y;
        d_kix[base] = k;
    }
}

// ---------------- synthesis: packed-f32x2 Reinsch oscillator --------------
// d_{t+1} = d_t + e*y_t ;  y_{t+1} = y_t + d_{t+1} ;  e = -4 sin^2(w/2)
__global__ __launch_bounds__(128, 7) void synth(float* __restrict__ out) {
    const int b  = blockIdx.z;
    const int d  = blockIdx.y * 128 + threadIdx.x;
    const int m  = blockIdx.x;
    const int base = (b * DD + d) * KSEL;
    const float2* rot = d_rot0 + m * NH;

    float ys[KSEL], dss[KSEL], es[KSEL];
#pragma unroll
    for (int r = 0; r < KSEL; r++) {
        int    k  = d_kix[base + r];
        float  c0 = d_c0[base + r];
        float  s0 = d_s0[base + r];
        float2 rk = rot[k];
        float  y  = fmaf(c0, rk.x, -s0 * rk.y);      // A cos(theta0)
        float  sn = fmaf(c0, rk.y,  s0 * rk.x);      // A sin(theta0)
        float  cw = d_cwT[k];
        float  sw = d_swT[k];
        float  yp = fmaf(y, cw, sn * sw);            // A cos(theta0 - w)
        ys[r]  = y;
        dss[r] = y - yp;
        es[r]  = d_eT[k];
    }

    u64 Y[8], D[8], E[8];
#pragma unroll
    for (int p = 0; p < 8; p++) {
        Y[p] = pk(ys[2 * p],  ys[2 * p + 1]);
        D[p] = pk(dss[2 * p], dss[2 * p + 1]);
        E[p] = pk(es[2 * p],  es[2 * p + 1]);
    }

    float* po = out + ((size_t)b * TT_LEN + m * TTILE) * DD + d;
#pragma unroll 4
    for (int tt = 0; tt < TTILE; tt++) {
        u64 q0, q1, q2, q3;
        F2ADD(q0, Y[0], Y[1]);
        F2ADD(q1, Y[2], Y[3]);
        F2ADD(q2, Y[4], Y[5]);
        F2ADD(q3, Y[6], Y[7]);
        F2ADD(q0, q0, q1);
        F2ADD(q2, q2, q3);
        F2ADD(q0, q0, q2);
        float lo, hi;
        upk(q0, lo, hi);
        po[(size_t)tt * DD] = lo + hi;

        // Reinsch advance: D += E*Y ; Y += D
#pragma unroll
        for (int p = 0; p < 8; p++) {
            F2FMA(D[p], E[p], Y[p], D[p]);
            F2ADD(Y[p], Y[p], D[p]);
        }
    }
}

// ---------------- launch ---------------------------------------------------
extern "C" void kernel_launch(void* const* d_in, const int* in_sizes, int n_in,
                              void* d_out, int out_size) {
    const float* x = (const float*)d_in[0];
    float* out = (float*)d_out;

    init_tables<<<64, 256>>>();
    transpose<<<dim3(TT_LEN / 32, DD / 32, BB), dim3(32, 8)>>>(x);
    analyze<<<BB * DD / 4, 256>>>();
    synth<<<dim3(NM, DD / 128, BB), 128>>>(out);
}

// round 9
// speedup vs baseline: 1.1495x; 1.0099x over previous
#include <cuda_runtime.h>
#include <math.h>
#include <stdint.h>

#define BB 32
#define TT_LEN 2048
#define DD 512
#define NH 1024        // complex FFT length (real length 2048)
#define KSEL 16
#define TTILE 256
#define NM (TT_LEN / TTILE)   // 8
#define PI_D 3.14159265358979323846

// padded smem indexing (pad every 16 float2): conflict-free for all three
// access patterns (stride-16 writes, u+64q"+256q reads, stage-B writes)
#define IDX(i) ((i) + ((i) >> 4))
#define PADN (NH + NH / 16)   // 1088

// ---------------- device scratch ------------------------------------------
__device__ float  d_xt[(size_t)BB * DD * TT_LEN];   // transposed input [b][d][t]
__device__ float2 d_twf[256];        // w   = exp(-2pi i j / 1024)
__device__ float2 d_twf2[256];       // w^2
__device__ float2 d_twf3[256];       // w^3
__device__ float2 d_twu[NH];         // untangle twiddles exp(-2pi i k / 2048)
__device__ float  d_cwT[NH];         // cos(omega_k)
__device__ float  d_swT[NH];         // sin(omega_k)
__device__ float  d_eT[NH];          // -4 sin^2(omega_k/2)  (Reinsch coefficient)
__device__ float2 d_rot0[NM * NH];   // e^{i omega_k * TTILE * m}
__device__ float  d_c0[BB * DD * KSEL];
__device__ float  d_s0[BB * DD * KSEL];
__device__ int    d_kix[BB * DD * KSEL];

// ---------------- packed f32x2 helpers ------------------------------------
typedef unsigned long long u64;
__device__ __forceinline__ u64 pk(float lo, float hi) {
    u64 r; asm("mov.b64 %0,{%1,%2};" : "=l"(r) : "f"(lo), "f"(hi)); return r;
}
__device__ __forceinline__ void upk(u64 v, float& lo, float& hi) {
    asm("mov.b64 {%0,%1},%2;" : "=f"(lo), "=f"(hi) : "l"(v));
}
#define F2ADD(d,a,b)   asm("add.rn.f32x2 %0,%1,%2;"    : "=l"(d) : "l"(a), "l"(b))
#define F2FMA(d,a,b,c) asm("fma.rn.f32x2 %0,%1,%2,%3;" : "=l"(d) : "l"(a), "l"(b), "l"(c))

// ---------------- init: all tables (double precision) ---------------------
__global__ void init_tables() {
    int gid = blockIdx.x * blockDim.x + threadIdx.x;   // 64*256 = 16384
    if (gid < 256) {
        double a = -2.0 * PI_D * (double)gid / (double)NH;
        d_twf[gid]  = make_float2((float)cos(a), (float)sin(a));
        d_twf2[gid] = make_float2((float)cos(2 * a), (float)sin(2 * a));
        d_twf3[gid] = make_float2((float)cos(3 * a), (float)sin(3 * a));
    }
    if (gid < NH) {
        double a = -2.0 * PI_D * (double)gid / (double)(2 * NH);
        d_twu[gid] = make_float2((float)cos(a), (float)sin(a));
        double om = 2.0 * PI_D * (double)gid / ((double)TT_LEN * (double)(TT_LEN - 1));
        d_cwT[gid] = (float)cos(om);
        d_swT[gid] = (float)sin(om);
        double sh = sin(om * 0.5);
        d_eT[gid]  = (float)(-4.0 * sh * sh);
    }
    if (gid < NM * NH) {
        int m = gid >> 10, k = gid & (NH - 1);
        double om = 2.0 * PI_D * (double)k / ((double)TT_LEN * (double)(TT_LEN - 1));
        double a = om * (double)(TTILE * m);
        d_rot0[gid] = make_float2((float)cos(a), (float)sin(a));
    }
}

// ---------------- transpose: x[b][t][d] -> d_xt[b][d][t] -------------------
__global__ __launch_bounds__(256) void transpose(const float* __restrict__ x) {
    __shared__ float tile[32][33];
    const int b  = blockIdx.z;
    const int t0 = blockIdx.x * 32;
    const int d0 = blockIdx.y * 32;
    const int lx = threadIdx.x;
    const int ly = threadIdx.y;
#pragma unroll
    for (int i = 0; i < 32; i += 8)
        tile[ly + i][lx] = x[((size_t)b * TT_LEN + t0 + ly + i) * DD + d0 + lx];
    __syncthreads();
#pragma unroll
    for (int i = 0; i < 32; i += 8)
        d_xt[((size_t)b * DD + d0 + ly + i) * TT_LEN + t0 + lx] = tile[lx][ly + i];
}

__device__ __forceinline__ float2 cmulf(float2 a, float2 b) {
    return make_float2(a.x * b.x - a.y * b.y, a.x * b.y + a.y * b.x);
}
__device__ __forceinline__ float2 cadd(float2 a, float2 b) { return make_float2(a.x + b.x, a.y + b.y); }
__device__ __forceinline__ float2 csub(float2 a, float2 b) { return make_float2(a.x - b.x, a.y - b.y); }

// radix-4 butterfly with twiddles (w, w^2, w^3)
__device__ __forceinline__ void bfly4(float2 a, float2 b, float2 c, float2 d,
                                      float2 w1, float2 w2, float2 w3,
                                      float2& o0, float2& o1, float2& o2, float2& o3) {
    float2 t0 = cadd(a, c);
    float2 t1 = csub(a, c);
    float2 t2 = cadd(b, d);
    float2 e  = csub(b, d);
    float2 t3 = make_float2(e.y, -e.x);   // -i*(b-d)
    o0 = cadd(t0, t2);
    o1 = cmulf(w1, cadd(t1, t3));
    o2 = cmulf(w2, csub(t0, t2));
    o3 = cmulf(w3, csub(t1, t3));
}

// Real-FFT bin k (1..1023) from packed complex spectrum Z (padded layout).
__device__ __forceinline__ float2 untangle(const float2* Z, int k) {
    float2 A  = Z[IDX(k)];
    float2 Bv = Z[IDX(NH - k)];
    float2 Bc = make_float2(Bv.x, -Bv.y);
    float2 E  = make_float2(0.5f * (A.x + Bc.x), 0.5f * (A.y + Bc.y));
    float2 Od = make_float2(A.x - Bc.x, A.y - Bc.y);
    float2 O  = make_float2(0.5f * Od.y, -0.5f * Od.x);
    float2 eo = cmulf(d_twu[k], O);
    return make_float2(E.x + eo.x, E.y + eo.y);
}

// ---------------- analysis: fused-stage FFT, 4 channels / block -----------
// 64 threads per channel, 16 complex points per thread.
// launch_bounds(256,4): 64-reg cap -> 4 resident blocks (was reg-limited to 3).
__global__ __launch_bounds__(256, 4) void analyze() {
    __shared__ float2   buf[4][PADN];
    __shared__ unsigned cand_v[4][8 * KSEL];
    __shared__ int      cand_k[4][8 * KSEL];
    __shared__ int      sel[4][KSEL];

    const int tid = threadIdx.x;
    const int u   = tid & 63;      // thread within channel
    const int c   = tid >> 6;      // channel within block
    const int ch  = blockIdx.x * 4 + c;
    const float2* row = (const float2*)(d_xt + (size_t)ch * TT_LEN);
    float2* B = buf[c];

    // ---- stage pair A: pass M=1 then M=4, fused in registers ----
    {
        float2 V[4][4];
#pragma unroll
        for (int qq = 0; qq < 4; qq++) {       // pass-1 thread t = u + 64*qq
            int t = u + 64 * qq;
            float2 a  = row[t];
            float2 b  = row[t + 256];
            float2 cc = row[t + 512];
            float2 dd = row[t + 768];
            bfly4(a, b, cc, dd, d_twf[t], d_twf2[t], d_twf3[t],
                  V[qq][0], V[qq][1], V[qq][2], V[qq][3]);
        }
        float2 w1 = d_twf[4 * u], w2 = d_twf2[4 * u], w3 = d_twf3[4 * u];
#pragma unroll
        for (int lam = 0; lam < 4; lam++) {    // pass-4 thread t' = 4u + lam
            float2 o0, o1, o2, o3;
            bfly4(V[0][lam], V[1][lam], V[2][lam], V[3][lam], w1, w2, w3,
                  o0, o1, o2, o3);
            B[IDX(16 * u +  0 + lam)] = o0;
            B[IDX(16 * u +  4 + lam)] = o1;
            B[IDX(16 * u +  8 + lam)] = o2;
            B[IDX(16 * u + 12 + lam)] = o3;
        }
    }
    __syncthreads();

    // ---- stage pair B: pass M=16 then M=64, fused; JIT smem reads ----
    // Reads happen before the barrier; all writes after. Live set = V only.
    {
        const int ub = u & ~15;                 // 16*h'
        float2 V[4][4];
#pragma unroll
        for (int qq = 0; qq < 4; qq++) {        // pass-16 thread t = u + 64*qq
            float2 r0 = B[IDX(u + 64 * qq)];
            float2 r1 = B[IDX(u + 64 * qq + 256)];
            float2 r2 = B[IDX(u + 64 * qq + 512)];
            float2 r3 = B[IDX(u + 64 * qq + 768)];
            int j = ub + 64 * qq;
            bfly4(r0, r1, r2, r3, d_twf[j], d_twf2[j], d_twf3[j],
                  V[qq][0], V[qq][1], V[qq][2], V[qq][3]);
        }
        __syncthreads();                        // all reads before any write

        int j2 = 4 * ub;
        float2 w1 = d_twf[j2], w2 = d_twf2[j2], w3 = d_twf3[j2];
        int basei = 16 * ub + (u & 15);
#pragma unroll
        for (int lam = 0; lam < 4; lam++) {     // pass-64 thread t' = 64h'+16lam+l
            float2 o0, o1, o2, o3;
            bfly4(V[0][lam], V[1][lam], V[2][lam], V[3][lam], w1, w2, w3,
                  o0, o1, o2, o3);
            B[IDX(basei + 16 * lam +   0)] = o0;
            B[IDX(basei + 16 * lam +  64)] = o1;
            B[IDX(basei + 16 * lam + 128)] = o2;
            B[IDX(basei + 16 * lam + 192)] = o3;
        }
    }
    __syncthreads();

    // ---- final pass M=256: per-thread in place (read set == write set) ----
#pragma unroll
    for (int qq = 0; qq < 4; qq++) {
        int t = u + 64 * qq;
        float2 a  = B[IDX(t)];
        float2 b  = B[IDX(t + 256)];
        float2 cc = B[IDX(t + 512)];
        float2 dd = B[IDX(t + 768)];
        float2 t0 = cadd(a, cc);
        float2 t1 = csub(a, cc);
        float2 t2 = cadd(b, dd);
        float2 e  = csub(b, dd);
        float2 t3 = make_float2(e.y, -e.x);
        B[IDX(t)]       = cadd(t0, t2);
        B[IDX(t + 256)] = cadd(t1, t3);
        B[IDX(t + 512)] = csub(t0, t2);
        B[IDX(t + 768)] = csub(t1, t3);
    }
    __syncthreads();
    // spectra for 4 channels in buf[0..3] (natural order, padded)

    // ---- mags: 4 bins per channel per thread, 4 channels ----
    unsigned uv[4][4];
    int      kv[4][4];
#pragma unroll
    for (int cc = 0; cc < 4; cc++) {
        const float2* Z = buf[cc];
        int b0 = tid, b1 = tid + 256, b2 = tid + 512, b3 = tid + 768;
        float2 X;
        unsigned m0;
        if (tid == 0) m0 = 0u;
        else { X = untangle(Z, b0); m0 = __float_as_uint(X.x * X.x + X.y * X.y); }
        X = untangle(Z, b1); unsigned m1 = __float_as_uint(X.x * X.x + X.y * X.y);
        X = untangle(Z, b2); unsigned m2 = __float_as_uint(X.x * X.x + X.y * X.y);
        X = untangle(Z, b3); unsigned m3 = __float_as_uint(X.x * X.x + X.y * X.y);
#define CSWP(a, b, ka, kb) if (a < b) { unsigned tu = a; a = b; b = tu; int tk = ka; ka = kb; kb = tk; }
        CSWP(m0, m1, b0, b1)
        CSWP(m2, m3, b2, b3)
        CSWP(m0, m2, b0, b2)
        CSWP(m1, m3, b1, b3)
        CSWP(m1, m2, b1, b2)
#undef CSWP
        uv[cc][0] = m0; uv[cc][1] = m1; uv[cc][2] = m2; uv[cc][3] = m3;
        kv[cc][0] = b0; kv[cc][1] = b1; kv[cc][2] = b2; kv[cc][3] = b3;
    }

    const int lane = tid & 31;
    const int warp = tid >> 5;
    const unsigned FULL = 0xffffffffu;

    // phase 1: per-warp top-16, 4 independent REDUX streams (one per channel)
    for (int r = 0; r < KSEL; r++) {
#pragma unroll
        for (int cc = 0; cc < 4; cc++) {
            unsigned mx = __reduce_max_sync(FULL, uv[cc][0]);
            unsigned ball = __ballot_sync(FULL, uv[cc][0] == mx);
            int wl = __ffs((int)ball) - 1;
            if (lane == wl) {
                cand_v[cc][warp * KSEL + r] = uv[cc][0];
                cand_k[cc][warp * KSEL + r] = kv[cc][0];
                uv[cc][0] = uv[cc][1]; kv[cc][0] = kv[cc][1];
                uv[cc][1] = uv[cc][2]; kv[cc][1] = kv[cc][2];
                uv[cc][2] = uv[cc][3]; kv[cc][2] = kv[cc][3];
                uv[cc][3] = 0u;
            }
        }
    }
    __syncthreads();

    // phase 2: warps 0-3 merge channels 0-3 in parallel
    if (warp < 4) {
        const int cc = warp;
        int ptr = 0, curk = 0;
        unsigned hv = 0u;
        if (lane < 8) { hv = cand_v[cc][lane * KSEL]; curk = cand_k[cc][lane * KSEL]; }
        for (int r = 0; r < KSEL; r++) {
            unsigned mx = __reduce_max_sync(FULL, hv);
            unsigned ball = __ballot_sync(FULL, hv == mx);
            int wl = __ffs((int)ball) - 1;
            int kwin = __shfl_sync(FULL, curk, wl);
            if (lane == 0) sel[cc][r] = kwin;
            if (lane == wl) {
                ptr++;
                if (ptr < KSEL) {
                    hv = cand_v[cc][lane * KSEL + ptr];
                    curk = cand_k[cc][lane * KSEL + ptr];
                } else {
                    hv = 0u;
                }
            }
        }
    }
    __syncthreads();

    // emit: warp w, lanes 0-15 -> channel w
    if (warp < 4 && lane < KSEL) {
        int k = sel[warp][lane];
        float2 Xk = untangle(buf[warp], k);
        int base = (blockIdx.x * 4 + warp) * KSEL + lane;
        d_c0[base]  = Xk.x;
        d_s0[base]  = Xk.y;
        d_kix[base] = k;
    }
}

// ---------------- synthesis: packed-f32x2 Reinsch oscillator --------------
// d_{t+1} = d_t + e*y_t ;  y_{t+1} = y_t + d_{t+1} ;  e = -4 sin^2(w/2)
__global__ __launch_bounds__(128, 7) void synth(float* __restrict__ out) {
    const int b  = blockIdx.z;
    const int d  = blockIdx.y * 128 + threadIdx.x;
    const int m  = blockIdx.x;
    const int base = (b * DD + d) * KSEL;
    const float2* rot = d_rot0 + m * NH;

    float ys[KSEL], dss[KSEL], es[KSEL];
#pragma unroll
    for (int r = 0; r < KSEL; r++) {
        int    k  = d_kix[base + r];
        float  c0 = d_c0[base + r];
        float  s0 = d_s0[base + r];
        float2 rk = rot[k];
        float  y  = fmaf(c0, rk.x, -s0 * rk.y);      // A cos(theta0)
        float  sn = fmaf(c0, rk.y,  s0 * rk.x);      // A sin(theta0)
        float  cw = d_cwT[k];
        float  sw = d_swT[k];
        float  yp = fmaf(y, cw, sn * sw);            // A cos(theta0 - w)
        ys[r]  = y;
        dss[r] = y - yp;
        es[r]  = d_eT[k];
    }

    u64 Y[8], D[8], E[8];
#pragma unroll
    for (int p = 0; p < 8; p++) {
        Y[p] = pk(ys[2 * p],  ys[2 * p + 1]);
        D[p] = pk(dss[2 * p], dss[2 * p + 1]);
        E[p] = pk(es[2 * p],  es[2 * p + 1]);
    }

    float* po = out + ((size_t)b * TT_LEN + m * TTILE) * DD + d;
#pragma unroll 4
    for (int tt = 0; tt < TTILE; tt++) {
        u64 q0, q1, q2, q3;
        F2ADD(q0, Y[0], Y[1]);
        F2ADD(q1, Y[2], Y[3]);
        F2ADD(q2, Y[4], Y[5]);
        F2ADD(q3, Y[6], Y[7]);
        F2ADD(q0, q0, q1);
        F2ADD(q2, q2, q3);
        F2ADD(q0, q0, q2);
        float lo, hi;
        upk(q0, lo, hi);
        po[(size_t)tt * DD] = lo + hi;

        // Reinsch advance: D += E*Y ; Y += D
#pragma unroll
        for (int p = 0; p < 8; p++) {
            F2FMA(D[p], E[p], Y[p], D[p]);
            F2ADD(Y[p], Y[p], D[p]);
        }
    }
}

// ---------------- launch ---------------------------------------------------
extern "C" void kernel_launch(void* const* d_in, const int* in_sizes, int n_in,
                              void* d_out, int out_size) {
    const float* x = (const float*)d_in[0];
    float* out = (float*)d_out;

    init_tables<<<64, 256>>>();
    transpose<<<dim3(TT_LEN / 32, DD / 32, BB), dim3(32, 8)>>>(x);
    analyze<<<BB * DD / 4, 256>>>();
    synth<<<dim3(NM, DD / 128, BB), 128>>>(out);
}

// round 10
// speedup vs baseline: 1.2063x; 1.0494x over previous
#include <cuda_runtime.h>
#include <math.h>
#include <stdint.h>

#define BB 32
#define TT_LEN 2048
#define DD 512
#define NH 1024        // complex FFT length (real length 2048)
#define KSEL 16
#define TTILE 256
#define NM (TT_LEN / TTILE)   // 8
#define PI_D 3.14159265358979323846

// padded smem indexing (pad every 16 float2)
#define IDX(i) ((i) + ((i) >> 4))
#define PADN (NH + NH / 16)   // 1088
#define SPITCH 2184           // staging float pitch per channel (skew 8 mod 32)

// ---------------- device scratch ------------------------------------------
__device__ float2 d_twf[256];        // w   = exp(-2pi i j / 1024)
__device__ float2 d_twf2[256];       // w^2
__device__ float2 d_twf3[256];       // w^3
__device__ float2 d_twu[NH];         // untangle twiddles exp(-2pi i k / 2048)
__device__ float  d_cwT[NH];         // cos(omega_k)
__device__ float  d_swT[NH];         // sin(omega_k)
__device__ float  d_eT[NH];          // -4 sin^2(omega_k/2)  (Reinsch coefficient)
__device__ float2 d_rot0[NM * NH];   // e^{i omega_k * TTILE * m}
__device__ float  d_c0[BB * DD * KSEL];
__device__ float  d_s0[BB * DD * KSEL];
__device__ int    d_kix[BB * DD * KSEL];

// ---------------- packed f32x2 helpers ------------------------------------
typedef unsigned long long u64;
__device__ __forceinline__ u64 pk(float lo, float hi) {
    u64 r; asm("mov.b64 %0,{%1,%2};" : "=l"(r) : "f"(lo), "f"(hi)); return r;
}
__device__ __forceinline__ void upk(u64 v, float& lo, float& hi) {
    asm("mov.b64 {%0,%1},%2;" : "=f"(lo), "=f"(hi) : "l"(v));
}
#define F2ADD(d,a,b)   asm("add.rn.f32x2 %0,%1,%2;"    : "=l"(d) : "l"(a), "l"(b))
#define F2FMA(d,a,b,c) asm("fma.rn.f32x2 %0,%1,%2,%3;" : "=l"(d) : "l"(a), "l"(b), "l"(c))

// ---------------- init: all tables (double precision) ---------------------
__global__ void init_tables() {
    int gid = blockIdx.x * blockDim.x + threadIdx.x;   // 64*256 = 16384
    if (gid < 256) {
        double a = -2.0 * PI_D * (double)gid / (double)NH;
        d_twf[gid]  = make_float2((float)cos(a), (float)sin(a));
        d_twf2[gid] = make_float2((float)cos(2 * a), (float)sin(2 * a));
        d_twf3[gid] = make_float2((float)cos(3 * a), (float)sin(3 * a));
    }
    if (gid < NH) {
        double a = -2.0 * PI_D * (double)gid / (double)(2 * NH);
        d_twu[gid] = make_float2((float)cos(a), (float)sin(a));
        double om = 2.0 * PI_D * (double)gid / ((double)TT_LEN * (double)(TT_LEN - 1));
        d_cwT[gid] = (float)cos(om);
        d_swT[gid] = (float)sin(om);
        double sh = sin(om * 0.5);
        d_eT[gid]  = (float)(-4.0 * sh * sh);
    }
    if (gid < NM * NH) {
        int m = gid >> 10, k = gid & (NH - 1);
        double om = 2.0 * PI_D * (double)k / ((double)TT_LEN * (double)(TT_LEN - 1));
        double a = om * (double)(TTILE * m);
        d_rot0[gid] = make_float2((float)cos(a), (float)sin(a));
    }
}

__device__ __forceinline__ float2 cmulf(float2 a, float2 b) {
    return make_float2(a.x * b.x - a.y * b.y, a.x * b.y + a.y * b.x);
}
__device__ __forceinline__ float2 cadd(float2 a, float2 b) { return make_float2(a.x + b.x, a.y + b.y); }
__device__ __forceinline__ float2 csub(float2 a, float2 b) { return make_float2(a.x - b.x, a.y - b.y); }

// radix-4 butterfly with twiddles (w, w^2, w^3)
__device__ __forceinline__ void bfly4(float2 a, float2 b, float2 c, float2 d,
                                      float2 w1, float2 w2, float2 w3,
                                      float2& o0, float2& o1, float2& o2, float2& o3) {
    float2 t0 = cadd(a, c);
    float2 t1 = csub(a, c);
    float2 t2 = cadd(b, d);
    float2 e  = csub(b, d);
    float2 t3 = make_float2(e.y, -e.x);   // -i*(b-d)
    o0 = cadd(t0, t2);
    o1 = cmulf(w1, cadd(t1, t3));
    o2 = cmulf(w2, csub(t0, t2));
    o3 = cmulf(w3, csub(t1, t3));
}

// Real-FFT bin k (1..1023) from packed complex spectrum Z (padded layout).
__device__ __forceinline__ float2 untangle(const float2* Z, int k) {
    float2 A  = Z[IDX(k)];
    float2 Bv = Z[IDX(NH - k)];
    float2 Bc = make_float2(Bv.x, -Bv.y);
    float2 E  = make_float2(0.5f * (A.x + Bc.x), 0.5f * (A.y + Bc.y));
    float2 Od = make_float2(A.x - Bc.x, A.y - Bc.y);
    float2 O  = make_float2(0.5f * Od.y, -0.5f * Od.x);
    float2 eo = cmulf(d_twu[k], O);
    return make_float2(E.x + eo.x, E.y + eo.y);
}

// ---------------- analysis: fused transpose + FFT, 4 channels / block -----
// Direct sector-granular loads from x (no separate transpose kernel).
// Staging lives inside the FFT buffer; pass A reads it all before writing.
__global__ __launch_bounds__(256, 4) void analyze(const float* __restrict__ x) {
    __shared__ float2   buf[4][PADN];
    __shared__ unsigned cand_v[4][8 * KSEL];
    __shared__ int      cand_k[4][8 * KSEL];
    __shared__ int      sel[4][KSEL];

    const int tid = threadIdx.x;
    const int u   = tid & 63;      // thread within channel
    const int c   = tid >> 6;      // channel within block
    float2* B = buf[c];
    float*  Fs = (float*)(&buf[0][0]);

    // ---- load + transpose into staging (skewed float layout) ----
    // Block covers channels ch0..ch0+3 = batch b, d = d0..d0+3.
    {
        const int b4  = blockIdx.x >> 7;            // batch
        const int col = (blockIdx.x & 127) * 2;     // float2 column base (d0/2)
        const float2* xr = (const float2*)x;
        const int dp = tid & 1;
        const int tl = tid >> 1;
        size_t rowbase = ((size_t)b4 * TT_LEN) * 256 + (size_t)(col + dp);
#pragma unroll
        for (int it = 0; it < 16; it++) {
            int t = tl + 128 * it;
            float2 v = xr[rowbase + (size_t)t * 256];
            Fs[(2 * dp)     * SPITCH + t] = v.x;    // channel 2dp
            Fs[(2 * dp + 1) * SPITCH + t] = v.y;    // channel 2dp+1
        }
    }
    __syncthreads();

    // ---- stage pair A: pass M=1 then M=4, fused; reads staging first ----
    {
        const float2* Sc = (const float2*)(Fs + c * SPITCH);
        float2 V[4][4];
#pragma unroll
        for (int qq = 0; qq < 4; qq++) {       // pass-1 thread t = u + 64*qq
            int t = u + 64 * qq;
            float2 a  = Sc[t];
            float2 b  = Sc[t + 256];
            float2 cc = Sc[t + 512];
            float2 dd = Sc[t + 768];
            bfly4(a, b, cc, dd, d_twf[t], d_twf2[t], d_twf3[t],
                  V[qq][0], V[qq][1], V[qq][2], V[qq][3]);
        }
        __syncthreads();                       // staging reads done before writes

        float2 w1 = d_twf[4 * u], w2 = d_twf2[4 * u], w3 = d_twf3[4 * u];
#pragma unroll
        for (int lam = 0; lam < 4; lam++) {    // pass-4 thread t' = 4u + lam
            float2 o0, o1, o2, o3;
            bfly4(V[0][lam], V[1][lam], V[2][lam], V[3][lam], w1, w2, w3,
                  o0, o1, o2, o3);
            B[IDX(16 * u +  0 + lam)] = o0;
            B[IDX(16 * u +  4 + lam)] = o1;
            B[IDX(16 * u +  8 + lam)] = o2;
            B[IDX(16 * u + 12 + lam)] = o3;
        }
    }
    __syncthreads();

    // ---- stage pair B: pass M=16 then M=64, fused; JIT smem reads ----
    {
        const int ub = u & ~15;                 // 16*h'
        float2 V[4][4];
#pragma unroll
        for (int qq = 0; qq < 4; qq++) {        // pass-16 thread t = u + 64*qq
            float2 r0 = B[IDX(u + 64 * qq)];
            float2 r1 = B[IDX(u + 64 * qq + 256)];
            float2 r2 = B[IDX(u + 64 * qq + 512)];
            float2 r3 = B[IDX(u + 64 * qq + 768)];
            int j = ub + 64 * qq;
            bfly4(r0, r1, r2, r3, d_twf[j], d_twf2[j], d_twf3[j],
                  V[qq][0], V[qq][1], V[qq][2], V[qq][3]);
        }
        __syncthreads();                        // all reads before any write

        int j2 = 4 * ub;
        float2 w1 = d_twf[j2], w2 = d_twf2[j2], w3 = d_twf3[j2];
        int basei = 16 * ub + (u & 15);
#pragma unroll
        for (int lam = 0; lam < 4; lam++) {     // pass-64 thread t' = 64h'+16lam+l
            float2 o0, o1, o2, o3;
            bfly4(V[0][lam], V[1][lam], V[2][lam], V[3][lam], w1, w2, w3,
                  o0, o1, o2, o3);
            B[IDX(basei + 16 * lam +   0)] = o0;
            B[IDX(basei + 16 * lam +  64)] = o1;
            B[IDX(basei + 16 * lam + 128)] = o2;
            B[IDX(basei + 16 * lam + 192)] = o3;
        }
    }
    __syncthreads();

    // ---- final pass M=256: per-thread in place (read set == write set) ----
#pragma unroll
    for (int qq = 0; qq < 4; qq++) {
        int t = u + 64 * qq;
        float2 a  = B[IDX(t)];
        float2 b  = B[IDX(t + 256)];
        float2 cc = B[IDX(t + 512)];
        float2 dd = B[IDX(t + 768)];
        float2 t0 = cadd(a, cc);
        float2 t1 = csub(a, cc);
        float2 t2 = cadd(b, dd);
        float2 e  = csub(b, dd);
        float2 t3 = make_float2(e.y, -e.x);
        B[IDX(t)]       = cadd(t0, t2);
        B[IDX(t + 256)] = cadd(t1, t3);
        B[IDX(t + 512)] = csub(t0, t2);
        B[IDX(t + 768)] = csub(t1, t3);
    }
    __syncthreads();
    // spectra for 4 channels in buf[0..3] (natural order, padded)

    // ---- mags: 4 bins per channel per thread, 4 channels ----
    unsigned uv[4][4];
    int      kv[4][4];
#pragma unroll
    for (int cc = 0; cc < 4; cc++) {
        const float2* Z = buf[cc];
        int b0 = tid, b1 = tid + 256, b2 = tid + 512, b3 = tid + 768;
        float2 X;
        unsigned m0;
        if (tid == 0) m0 = 0u;
        else { X = untangle(Z, b0); m0 = __float_as_uint(X.x * X.x + X.y * X.y); }
        X = untangle(Z, b1); unsigned m1 = __float_as_uint(X.x * X.x + X.y * X.y);
        X = untangle(Z, b2); unsigned m2 = __float_as_uint(X.x * X.x + X.y * X.y);
        X = untangle(Z, b3); unsigned m3 = __float_as_uint(X.x * X.x + X.y * X.y);
#define CSWP(a, b, ka, kb) if (a < b) { unsigned tu = a; a = b; b = tu; int tk = ka; ka = kb; kb = tk; }
        CSWP(m0, m1, b0, b1)
        CSWP(m2, m3, b2, b3)
        CSWP(m0, m2, b0, b2)
        CSWP(m1, m3, b1, b3)
        CSWP(m1, m2, b1, b2)
#undef CSWP
        uv[cc][0] = m0; uv[cc][1] = m1; uv[cc][2] = m2; uv[cc][3] = m3;
        kv[cc][0] = b0; kv[cc][1] = b1; kv[cc][2] = b2; kv[cc][3] = b3;
    }

    const int lane = tid & 31;
    const int warp = tid >> 5;
    const unsigned FULL = 0xffffffffu;

    // phase 1: per-warp top-16, 4 independent REDUX streams (one per channel)
    for (int r = 0; r < KSEL; r++) {
#pragma unroll
        for (int cc = 0; cc < 4; cc++) {
            unsigned mx = __reduce_max_sync(FULL, uv[cc][0]);
            unsigned ball = __ballot_sync(FULL, uv[cc][0] == mx);
            int wl = __ffs((int)ball) - 1;
            if (lane == wl) {
                cand_v[cc][warp * KSEL + r] = uv[cc][0];
                cand_k[cc][warp * KSEL + r] = kv[cc][0];
                uv[cc][0] = uv[cc][1]; kv[cc][0] = kv[cc][1];
                uv[cc][1] = uv[cc][2]; kv[cc][1] = kv[cc][2];
                uv[cc][2] = uv[cc][3]; kv[cc][2] = kv[cc][3];
                uv[cc][3] = 0u;
            }
        }
    }
    __syncthreads();

    // phase 2: warps 0-3 merge channels 0-3 in parallel
    if (warp < 4) {
        const int cc = warp;
        int ptr = 0, curk = 0;
        unsigned hv = 0u;
        if (lane < 8) { hv = cand_v[cc][lane * KSEL]; curk = cand_k[cc][lane * KSEL]; }
        for (int r = 0; r < KSEL; r++) {
            unsigned mx = __reduce_max_sync(FULL, hv);
            unsigned ball = __ballot_sync(FULL, hv == mx);
            int wl = __ffs((int)ball) - 1;
            int kwin = __shfl_sync(FULL, curk, wl);
            if (lane == 0) sel[cc][r] = kwin;
            if (lane == wl) {
                ptr++;
                if (ptr < KSEL) {
                    hv = cand_v[cc][lane * KSEL + ptr];
                    curk = cand_k[cc][lane * KSEL + ptr];
                } else {
                    hv = 0u;
                }
            }
        }
    }
    __syncthreads();

    // emit: warp w, lanes 0-15 -> channel w
    if (warp < 4 && lane < KSEL) {
        int k = sel[warp][lane];
        float2 Xk = untangle(buf[warp], k);
        int base = (blockIdx.x * 4 + warp) * KSEL + lane;
        d_c0[base]  = Xk.x;
        d_s0[base]  = Xk.y;
        d_kix[base] = k;
    }
}

// ---------------- synthesis: packed-f32x2 Reinsch oscillator --------------
// d_{t+1} = d_t + e*y_t ;  y_{t+1} = y_t + d_{t+1} ;  e = -4 sin^2(w/2)
__global__ __launch_bounds__(128, 7) void synth(float* __restrict__ out) {
    const int b  = blockIdx.z;
    const int d  = blockIdx.y * 128 + threadIdx.x;
    const int m  = blockIdx.x;
    const int base = (b * DD + d) * KSEL;
    const float2* rot = d_rot0 + m * NH;

    float ys[KSEL], dss[KSEL], es[KSEL];
#pragma unroll
    for (int r = 0; r < KSEL; r++) {
        int    k  = d_kix[base + r];
        float  c0 = d_c0[base + r];
        float  s0 = d_s0[base + r];
        float2 rk = rot[k];
        float  y  = fmaf(c0, rk.x, -s0 * rk.y);      // A cos(theta0)
        float  sn = fmaf(c0, rk.y,  s0 * rk.x);      // A sin(theta0)
        float  cw = d_cwT[k];
        float  sw = d_swT[k];
        float  yp = fmaf(y, cw, sn * sw);            // A cos(theta0 - w)
        ys[r]  = y;
        dss[r] = y - yp;
        es[r]  = d_eT[k];
    }

    u64 Y[8], D[8], E[8];
#pragma unroll
    for (int p = 0; p < 8; p++) {
        Y[p] = pk(ys[2 * p],  ys[2 * p + 1]);
        D[p] = pk(dss[2 * p], dss[2 * p + 1]);
        E[p] = pk(es[2 * p],  es[2 * p + 1]);
    }

    float* po = out + ((size_t)b * TT_LEN + m * TTILE) * DD + d;
#pragma unroll 4
    for (int tt = 0; tt < TTILE; tt++) {
        u64 q0, q1, q2, q3;
        F2ADD(q0, Y[0], Y[1]);
        F2ADD(q1, Y[2], Y[3]);
        F2ADD(q2, Y[4], Y[5]);
        F2ADD(q3, Y[6], Y[7]);
        F2ADD(q0, q0, q1);
        F2ADD(q2, q2, q3);
        F2ADD(q0, q0, q2);
        float lo, hi;
        upk(q0, lo, hi);
        po[(size_t)tt * DD] = lo + hi;

        // Reinsch advance: D += E*Y ; Y += D
#pragma unroll
        for (int p = 0; p < 8; p++) {
            F2FMA(D[p], E[p], Y[p], D[p]);
            F2ADD(Y[p], Y[p], D[p]);
        }
    }
}

// ---------------- launch ---------------------------------------------------
extern "C" void kernel_launch(void* const* d_in, const int* in_sizes, int n_in,
                              void* d_out, int out_size) {
    const float* x = (const float*)d_in[0];
    float* out = (float*)d_out;

    init_tables<<<64, 256>>>();
    analyze<<<BB * DD / 4, 256>>>(x);
    synth<<<dim3(NM, DD / 128, BB), 128>>>(out);
}

// round 11
// speedup vs baseline: 1.3297x; 1.1023x over previous
#include <cuda_runtime.h>
#include <math.h>
#include <stdint.h>

#define BB 32
#define TT_LEN 2048
#define DD 512
#define NH 1024        // complex FFT length (real length 2048)
#define KSEL 16
#define TTILE 256
#define NM (TT_LEN / TTILE)   // 8
#define PI_D 3.14159265358979323846

// padded smem indexing (pad every 16 float2)
#define IDX(i) ((i) + ((i) >> 4))
#define PADN (NH + NH / 16)   // 1088
#define SPITCH 2184           // staging float pitch per channel (skew 8 mod 32)

// ---------------- device scratch ------------------------------------------
__device__ float2 d_twf[256];        // w   = exp(-2pi i j / 1024)
__device__ float2 d_twf2[256];       // w^2
__device__ float2 d_twf3[256];       // w^3
__device__ float2 d_twu[NH];         // untangle twiddles exp(-2pi i k / 2048)
__device__ float  d_cwT[NH];         // cos(omega_k)
__device__ float  d_swT[NH];         // sin(omega_k)
__device__ float  d_eT[NH];          // -4 sin^2(omega_k/2)  (Reinsch coefficient)
__device__ float2 d_rot0[NM * NH];   // e^{i omega_k * TTILE * m}
__device__ float  d_c0[BB * DD * KSEL];
__device__ float  d_s0[BB * DD * KSEL];
__device__ int    d_kix[BB * DD * KSEL];

// ---------------- packed f32x2 helpers ------------------------------------
typedef unsigned long long u64;
__device__ __forceinline__ u64 pk(float lo, float hi) {
    u64 r; asm("mov.b64 %0,{%1,%2};" : "=l"(r) : "f"(lo), "f"(hi)); return r;
}
__device__ __forceinline__ void upk(u64 v, float& lo, float& hi) {
    asm("mov.b64 {%0,%1},%2;" : "=f"(lo), "=f"(hi) : "l"(v));
}
#define F2ADD(d,a,b)   asm("add.rn.f32x2 %0,%1,%2;"    : "=l"(d) : "l"(a), "l"(b))
#define F2FMA(d,a,b,c) asm("fma.rn.f32x2 %0,%1,%2,%3;" : "=l"(d) : "l"(a), "l"(b), "l"(c))

// ---------------- init: range-split, <=1 fp64 sincos per thread -----------
// sections: [0,256) twf | [256,512) twf2 | [512,768) twf3 | [768,1792) twu
//           [1792,2816) cw/sw | [2816,3840) eT | [3840,12032) rot0
__global__ void init_tables() {
    int gid = blockIdx.x * blockDim.x + threadIdx.x;   // 47*256 = 12032
    if (gid < 256) {
        double a = -2.0 * PI_D * (double)gid / (double)NH;
        d_twf[gid] = make_float2((float)cos(a), (float)sin(a));
    } else if (gid < 512) {
        int j = gid - 256;
        double a = -4.0 * PI_D * (double)j / (double)NH;
        d_twf2[j] = make_float2((float)cos(a), (float)sin(a));
    } else if (gid < 768) {
        int j = gid - 512;
        double a = -6.0 * PI_D * (double)j / (double)NH;
        d_twf3[j] = make_float2((float)cos(a), (float)sin(a));
    } else if (gid < 1792) {
        int k = gid - 768;
        double a = -2.0 * PI_D * (double)k / (double)(2 * NH);
        d_twu[k] = make_float2((float)cos(a), (float)sin(a));
    } else if (gid < 2816) {
        int k = gid - 1792;
        double om = 2.0 * PI_D * (double)k / ((double)TT_LEN * (double)(TT_LEN - 1));
        d_cwT[k] = (float)cos(om);
        d_swT[k] = (float)sin(om);
    } else if (gid < 3840) {
        int k = gid - 2816;
        double om = 2.0 * PI_D * (double)k / ((double)TT_LEN * (double)(TT_LEN - 1));
        double sh = sin(om * 0.5);
        d_eT[k] = (float)(-4.0 * sh * sh);
    } else if (gid < 3840 + NM * NH) {
        int e = gid - 3840;
        int m = e >> 10, k = e & (NH - 1);
        double om = 2.0 * PI_D * (double)k / ((double)TT_LEN * (double)(TT_LEN - 1));
        double a = om * (double)(TTILE * m);
        d_rot0[e] = make_float2((float)cos(a), (float)sin(a));
    }
}

__device__ __forceinline__ float2 cmulf(float2 a, float2 b) {
    return make_float2(a.x * b.x - a.y * b.y, a.x * b.y + a.y * b.x);
}
__device__ __forceinline__ float2 cadd(float2 a, float2 b) { return make_float2(a.x + b.x, a.y + b.y); }
__device__ __forceinline__ float2 csub(float2 a, float2 b) { return make_float2(a.x - b.x, a.y - b.y); }

// radix-4 butterfly with twiddles (w, w^2, w^3)
__device__ __forceinline__ void bfly4(float2 a, float2 b, float2 c, float2 d,
                                      float2 w1, float2 w2, float2 w3,
                                      float2& o0, float2& o1, float2& o2, float2& o3) {
    float2 t0 = cadd(a, c);
    float2 t1 = csub(a, c);
    float2 t2 = cadd(b, d);
    float2 e  = csub(b, d);
    float2 t3 = make_float2(e.y, -e.x);   // -i*(b-d)
    o0 = cadd(t0, t2);
    o1 = cmulf(w1, cadd(t1, t3));
    o2 = cmulf(w2, csub(t0, t2));
    o3 = cmulf(w3, csub(t1, t3));
}

// Real-FFT bin k (1..1023) from packed complex spectrum Z (padded layout).
__device__ __forceinline__ float2 untangle(const float2* Z, int k) {
    float2 A  = Z[IDX(k)];
    float2 Bv = Z[IDX(NH - k)];
    float2 Bc = make_float2(Bv.x, -Bv.y);
    float2 E  = make_float2(0.5f * (A.x + Bc.x), 0.5f * (A.y + Bc.y));
    float2 Od = make_float2(A.x - Bc.x, A.y - Bc.y);
    float2 O  = make_float2(0.5f * Od.y, -0.5f * Od.x);
    float2 eo = cmulf(d_twu[k], O);
    return make_float2(E.x + eo.x, E.y + eo.y);
}

// Conjugate-pair magnitudes: one load pair -> |X(k)|^2 and |X(NH-k)|^2.
// X(k) = E + eO ; X(NH-k) = conj(E - eO).
__device__ __forceinline__ void mag_pair(const float2* Z, int k,
                                         unsigned& mk, unsigned& mnk) {
    float2 A  = Z[IDX(k)];
    float2 Bv = Z[IDX(NH - k)];
    float Ex = 0.5f * (A.x + Bv.x), Ey = 0.5f * (A.y - Bv.y);
    float Ox = 0.5f * (A.y + Bv.y), Oy = -0.5f * (A.x - Bv.x);
    float2 e = d_twu[k];
    float eox = e.x * Ox - e.y * Oy;
    float eoy = e.x * Oy + e.y * Ox;
    float px = Ex + eox, py = Ey + eoy;
    float qx = Ex - eox, qy = Ey - eoy;
    mk  = __float_as_uint(px * px + py * py);
    mnk = __float_as_uint(qx * qx + qy * qy);
}

// ---------------- analysis: fused transpose + FFT, 4 channels / block -----
__global__ __launch_bounds__(256, 4) void analyze(const float* __restrict__ x) {
    __shared__ float2   buf[4][PADN];
    __shared__ unsigned cand_v[4][8 * KSEL];
    __shared__ int      cand_k[4][8 * KSEL];
    __shared__ int      sel[4][KSEL];

    const int tid = threadIdx.x;
    const int u   = tid & 63;      // thread within channel
    const int c   = tid >> 6;      // channel within block
    float2* B = buf[c];
    float*  Fs = (float*)(&buf[0][0]);

    // ---- load + transpose into staging (skewed float layout) ----
    {
        const int b4  = blockIdx.x >> 7;            // batch
        const int col = (blockIdx.x & 127) * 2;     // float2 column base (d0/2)
        const float2* xr = (const float2*)x;
        const int dp = tid & 1;
        const int tl = tid >> 1;
        size_t rowbase = ((size_t)b4 * TT_LEN) * 256 + (size_t)(col + dp);
#pragma unroll
        for (int it = 0; it < 16; it++) {
            int t = tl + 128 * it;
            float2 v = xr[rowbase + (size_t)t * 256];
            Fs[(2 * dp)     * SPITCH + t] = v.x;    // channel 2dp
            Fs[(2 * dp + 1) * SPITCH + t] = v.y;    // channel 2dp+1
        }
    }
    __syncthreads();

    // ---- stage pair A: pass M=1 then M=4, fused; reads staging first ----
    {
        const float2* Sc = (const float2*)(Fs + c * SPITCH);
        float2 V[4][4];
#pragma unroll
        for (int qq = 0; qq < 4; qq++) {       // pass-1 thread t = u + 64*qq
            int t = u + 64 * qq;
            float2 a  = Sc[t];
            float2 b  = Sc[t + 256];
            float2 cc = Sc[t + 512];
            float2 dd = Sc[t + 768];
            bfly4(a, b, cc, dd, d_twf[t], d_twf2[t], d_twf3[t],
                  V[qq][0], V[qq][1], V[qq][2], V[qq][3]);
        }
        __syncthreads();                       // staging reads done before writes

        float2 w1 = d_twf[4 * u], w2 = d_twf2[4 * u], w3 = d_twf3[4 * u];
#pragma unroll
        for (int lam = 0; lam < 4; lam++) {    // pass-4 thread t' = 4u + lam
            float2 o0, o1, o2, o3;
            bfly4(V[0][lam], V[1][lam], V[2][lam], V[3][lam], w1, w2, w3,
                  o0, o1, o2, o3);
            B[IDX(16 * u +  0 + lam)] = o0;
            B[IDX(16 * u +  4 + lam)] = o1;
            B[IDX(16 * u +  8 + lam)] = o2;
            B[IDX(16 * u + 12 + lam)] = o3;
        }
    }
    __syncthreads();

    // ---- stage pair B: pass M=16 then M=64, fused; JIT smem reads ----
    {
        const int ub = u & ~15;                 // 16*h'
        float2 V[4][4];
#pragma unroll
        for (int qq = 0; qq < 4; qq++) {        // pass-16 thread t = u + 64*qq
            float2 r0 = B[IDX(u + 64 * qq)];
            float2 r1 = B[IDX(u + 64 * qq + 256)];
            float2 r2 = B[IDX(u + 64 * qq + 512)];
            float2 r3 = B[IDX(u + 64 * qq + 768)];
            int j = ub + 64 * qq;
            bfly4(r0, r1, r2, r3, d_twf[j], d_twf2[j], d_twf3[j],
                  V[qq][0], V[qq][1], V[qq][2], V[qq][3]);
        }
        __syncthreads();                        // all reads before any write

        int j2 = 4 * ub;
        float2 w1 = d_twf[j2], w2 = d_twf2[j2], w3 = d_twf3[j2];
        int basei = 16 * ub + (u & 15);
#pragma unroll
        for (int lam = 0; lam < 4; lam++) {     // pass-64 thread t' = 64h'+16lam+l
            float2 o0, o1, o2, o3;
            bfly4(V[0][lam], V[1][lam], V[2][lam], V[3][lam], w1, w2, w3,
                  o0, o1, o2, o3);
            B[IDX(basei + 16 * lam +   0)] = o0;
            B[IDX(basei + 16 * lam +  64)] = o1;
            B[IDX(basei + 16 * lam + 128)] = o2;
            B[IDX(basei + 16 * lam + 192)] = o3;
        }
    }
    __syncthreads();

    // ---- final pass M=256: per-thread in place ----
#pragma unroll
    for (int qq = 0; qq < 4; qq++) {
        int t = u + 64 * qq;
        float2 a  = B[IDX(t)];
        float2 b  = B[IDX(t + 256)];
        float2 cc = B[IDX(t + 512)];
        float2 dd = B[IDX(t + 768)];
        float2 t0 = cadd(a, cc);
        float2 t1 = csub(a, cc);
        float2 t2 = cadd(b, dd);
        float2 e  = csub(b, dd);
        float2 t3 = make_float2(e.y, -e.x);
        B[IDX(t)]       = cadd(t0, t2);
        B[IDX(t + 256)] = cadd(t1, t3);
        B[IDX(t + 512)] = csub(t0, t2);
        B[IDX(t + 768)] = csub(t1, t3);
    }
    __syncthreads();
    // spectra for 4 channels in buf[0..3]

    // ---- mags via conjugate pairs: thread t -> k=2t+1, 2t+2 (k in 1..512) ----
    unsigned uv[4][4];
    int      kv[4][4];
    const int k1 = 2 * tid + 1;
    const int k2 = 2 * tid + 2;
#pragma unroll
    for (int cc = 0; cc < 4; cc++) {
        const float2* Z = buf[cc];
        unsigned m0, m1, m2, m3;
        mag_pair(Z, k1, m0, m1);   // bins k1, NH-k1
        mag_pair(Z, k2, m2, m3);   // bins k2, NH-k2
        int b0 = k1, b1 = NH - k1, b2 = k2, b3 = NH - k2;
        if (k2 == 512) { m3 = 0u; }   // bin 512 self-paired: kill duplicate
#define CSWP(a, b, ka, kb) if (a < b) { unsigned tu = a; a = b; b = tu; int tk = ka; ka = kb; kb = tk; }
        CSWP(m0, m1, b0, b1)
        CSWP(m2, m3, b2, b3)
        CSWP(m0, m2, b0, b2)
        CSWP(m1, m3, b1, b3)
        CSWP(m1, m2, b1, b2)
#undef CSWP
        uv[cc][0] = m0; uv[cc][1] = m1; uv[cc][2] = m2; uv[cc][3] = m3;
        kv[cc][0] = b0; kv[cc][1] = b1; kv[cc][2] = b2; kv[cc][3] = b3;
    }

    const int lane = tid & 31;
    const int warp = tid >> 5;
    const unsigned FULL = 0xffffffffu;

    // phase 1: per-warp top-16, 4 independent REDUX streams (one per channel)
    for (int r = 0; r < KSEL; r++) {
#pragma unroll
        for (int cc = 0; cc < 4; cc++) {
            unsigned mx = __reduce_max_sync(FULL, uv[cc][0]);
            unsigned ball = __ballot_sync(FULL, uv[cc][0] == mx);
            int wl = __ffs((int)ball) - 1;
            if (lane == wl) {
                cand_v[cc][warp * KSEL + r] = uv[cc][0];
                cand_k[cc][warp * KSEL + r] = kv[cc][0];
                uv[cc][0] = uv[cc][1]; kv[cc][0] = kv[cc][1];
                uv[cc][1] = uv[cc][2]; kv[cc][1] = kv[cc][2];
                uv[cc][2] = uv[cc][3]; kv[cc][2] = kv[cc][3];
                uv[cc][3] = 0u;
            }
        }
    }
    __syncthreads();

    // phase 2: warps 0-3 merge channels 0-3 in parallel
    if (warp < 4) {
        const int cc = warp;
        int ptr = 0, curk = 0;
        unsigned hv = 0u;
        if (lane < 8) { hv = cand_v[cc][lane * KSEL]; curk = cand_k[cc][lane * KSEL]; }
        for (int r = 0; r < KSEL; r++) {
            unsigned mx = __reduce_max_sync(FULL, hv);
            unsigned ball = __ballot_sync(FULL, hv == mx);
            int wl = __ffs((int)ball) - 1;
            int kwin = __shfl_sync(FULL, curk, wl);
            if (lane == 0) sel[cc][r] = kwin;
            if (lane == wl) {
                ptr++;
                if (ptr < KSEL) {
                    hv = cand_v[cc][lane * KSEL + ptr];
                    curk = cand_k[cc][lane * KSEL + ptr];
                } else {
                    hv = 0u;
                }
            }
        }
    }
    __syncthreads();

    // emit: warp w, lanes 0-15 -> channel w
    if (warp < 4 && lane < KSEL) {
        int k = sel[warp][lane];
        float2 Xk = untangle(buf[warp], k);
        int base = (blockIdx.x * 4 + warp) * KSEL + lane;
        d_c0[base]  = Xk.x;
        d_s0[base]  = Xk.y;
        d_kix[base] = k;
    }
}

// ---------------- synthesis: packed-f32x2 Reinsch oscillator --------------
__global__ __launch_bounds__(128, 7) void synth(float* __restrict__ out) {
    const int b  = blockIdx.z;
    const int d  = blockIdx.y * 128 + threadIdx.x;
    const int m  = blockIdx.x;
    const int base = (b * DD + d) * KSEL;
    const float2* rot = d_rot0 + m * NH;

    float ys[KSEL], dss[KSEL], es[KSEL];
#pragma unroll
    for (int r = 0; r < KSEL; r++) {
        int    k  = d_kix[base + r];
        float  c0 = d_c0[base + r];
        float  s0 = d_s0[base + r];
        float2 rk = rot[k];
        float  y  = fmaf(c0, rk.x, -s0 * rk.y);      // A cos(theta0)
        float  sn = fmaf(c0, rk.y,  s0 * rk.x);      // A sin(theta0)
        float  cw = d_cwT[k];
        float  sw = d_swT[k];
        float  yp = fmaf(y, cw, sn * sw);            // A cos(theta0 - w)
        ys[r]  = y;
        dss[r] = y - yp;
        es[r]  = d_eT[k];
    }

    u64 Y[8], D[8], E[8];
#pragma unroll
    for (int p = 0; p < 8; p++) {
        Y[p] = pk(ys[2 * p],  ys[2 * p + 1]);
        D[p] = pk(dss[2 * p], dss[2 * p + 1]);
        E[p] = pk(es[2 * p],  es[2 * p + 1]);
    }

    float* po = out + ((size_t)b * TT_LEN + m * TTILE) * DD + d;
#pragma unroll 4
    for (int tt = 0; tt < TTILE; tt++) {
        u64 q0, q1, q2, q3;
        F2ADD(q0, Y[0], Y[1]);
        F2ADD(q1, Y[2], Y[3]);
        F2ADD(q2, Y[4], Y[5]);
        F2ADD(q3, Y[6], Y[7]);
        F2ADD(q0, q0, q1);
        F2ADD(q2, q2, q3);
        F2ADD(q0, q0, q2);
        float lo, hi;
        upk(q0, lo, hi);
        po[(size_t)tt * DD] = lo + hi;

        // Reinsch advance: D += E*Y ; Y += D
#pragma unroll
        for (int p = 0; p < 8; p++) {
            F2FMA(D[p], E[p], Y[p], D[p]);
            F2ADD(Y[p], Y[p], D[p]);
        }
    }
}

// ---------------- launch ---------------------------------------------------
extern "C" void kernel_launch(void* const* d_in, const int* in_sizes, int n_in,
                              void* d_out, int out_size) {
    const float* x = (const float*)d_in[0];
    float* out = (float*)d_out;

    init_tables<<<47, 256>>>();
    analyze<<<BB * DD / 4, 256>>>(x);
    synth<<<dim3(NM, DD / 128, BB), 128>>>(out);
}